// round 7
// baseline (speedup 1.0000x reference)
#include <cuda_runtime.h>
#include <cuda_bf16.h>
#include <math.h>
#include <stdint.h>

// ---------------- problem constants ----------------
#define TT   1024
#define HD   1024
#define NE   64
#define ID   512
#define KK   8
#define NG   8
#define TG   4
#define EG   8
#define CAP  512
#define RSCALE 2.5f

// ---------------- device scratch ----------------
__device__ int   g_topk_idx[TT * KK];
__device__ float g_topk_w[TT * KK];
__device__ int   g_counts[NE];
__device__ int   g_slot_tok[NE * CAP];
__device__ int   g_slot_aid[NE * CAP];
__device__ int   g_valid[TT * KK];
__device__ float g_G[(size_t)NE * CAP * ID];              // gate GEMM out (fp32)
__device__ __nv_bfloat16 g_h_hi[(size_t)NE * CAP * ID];   // swiglu hi
__device__ __nv_bfloat16 g_h_lo[(size_t)NE * CAP * ID];   // swiglu lo
__device__ float g_outa[(size_t)TT * KK * HD];            // per-assignment down out
__device__ float g_sG[(size_t)TT * ID];                   // shared gate out (fp32)
__device__ __nv_bfloat16 g_shh[(size_t)TT * ID];          // shared hidden hi
__device__ __nv_bfloat16 g_shl[(size_t)TT * ID];          // shared hidden lo

// ---------------- helpers ----------------
__device__ __forceinline__ uint32_t smem_u32(const void* p) {
    uint32_t a;
    asm("{ .reg .u64 t; cvta.to.shared.u64 t, %1; cvt.u32.u64 %0, t; }"
        : "=r"(a) : "l"(p));
    return a;
}

__device__ __forceinline__ void bsplit(float a, unsigned short& h, unsigned short& l) {
    __nv_bfloat16 hb = __float2bfloat16(a);
    __nv_bfloat16 lb = __float2bfloat16(a - __bfloat162float(hb));
    h = __bfloat16_as_ushort(hb);
    l = __bfloat16_as_ushort(lb);
}
__device__ __forceinline__ uint32_t pk(unsigned short a, unsigned short b) {
    return (uint32_t)a | ((uint32_t)b << 16);
}

__device__ __forceinline__ void ldsm4(uint32_t* r, uint32_t addr) {
    asm volatile("ldmatrix.sync.aligned.m8n8.x4.shared.b16 {%0,%1,%2,%3}, [%4];"
        : "=r"(r[0]), "=r"(r[1]), "=r"(r[2]), "=r"(r[3]) : "r"(addr));
}
__device__ __forceinline__ void ldsm4t(uint32_t* r, uint32_t addr) {
    asm volatile("ldmatrix.sync.aligned.m8n8.x4.trans.shared.b16 {%0,%1,%2,%3}, [%4];"
        : "=r"(r[0]), "=r"(r[1]), "=r"(r[2]), "=r"(r[3]) : "r"(addr));
}
__device__ __forceinline__ void mma16816(float* d, const uint32_t* a,
                                         uint32_t b0, uint32_t b1) {
    asm volatile(
        "mma.sync.aligned.m16n8k16.row.col.f32.bf16.bf16.f32 "
        "{%0,%1,%2,%3}, {%4,%5,%6,%7}, {%8,%9}, {%0,%1,%2,%3};"
        : "+f"(d[0]), "+f"(d[1]), "+f"(d[2]), "+f"(d[3])
        : "r"(a[0]), "r"(a[1]), "r"(a[2]), "r"(a[3]), "r"(b0), "r"(b1));
}

__device__ __forceinline__ float silu(float g) { return g / (1.f + expf(-g)); }

// ---------------- router ----------------
__global__ void router_kernel(const float* __restrict__ x,
                              const float* __restrict__ rw)
{
    const int t = blockIdx.x;
    __shared__ float xs[HD];
    __shared__ float sc[NE];
    __shared__ float ms[NE];
    __shared__ float gm[NG];
    __shared__ int   selg[NG];

    for (int i = threadIdx.x; i < HD; i += blockDim.x)
        xs[i] = x[(size_t)t * HD + i];
    __syncthreads();

    const int e = threadIdx.x;
    if (e < NE) {
        float acc = 0.f;
        #pragma unroll 8
        for (int h = 0; h < HD; ++h)
            acc = fmaf(xs[h], rw[(size_t)h * NE + e], acc);
        sc[e] = 1.f / (1.f + expf(-acc));
    }
    __syncthreads();

    if (threadIdx.x == 0) {
        for (int g = 0; g < NG; ++g) {
            float m = sc[g * EG];
            for (int j = 1; j < EG; ++j) m = fmaxf(m, sc[g * EG + j]);
            gm[g] = m; selg[g] = 0;
        }
        for (int r = 0; r < TG; ++r) {
            int bi = -1; float bv = -1e30f;
            for (int g = 0; g < NG; ++g)
                if (!selg[g] && gm[g] > bv) { bv = gm[g]; bi = g; }
            selg[bi] = 1;
        }
        for (int ee = 0; ee < NE; ++ee)
            ms[ee] = selg[ee / EG] ? sc[ee] : 0.0f;

        int   idx[KK];
        float val[KK];
        float sum = 0.f;
        for (int r = 0; r < KK; ++r) {
            int bi = 0; float bv = ms[0];
            for (int ee = 1; ee < NE; ++ee)
                if (ms[ee] > bv) { bv = ms[ee]; bi = ee; }
            idx[r] = bi; val[r] = bv; ms[bi] = -1.f; sum += bv;
        }
        const float inv = RSCALE / fmaxf(sum, 1e-9f);
        for (int r = 0; r < KK; ++r) {
            g_topk_idx[t * KK + r] = idx[r];
            g_topk_w[t * KK + r]   = val[r] * inv;
        }
    }
}

__global__ void zero_counts_kernel()
{
    if (threadIdx.x < NE) g_counts[threadIdx.x] = 0;
}

__global__ void assign_kernel()
{
    const int a = blockIdx.x * blockDim.x + threadIdx.x;
    if (a >= TT * KK) return;
    const int e = g_topk_idx[a];
    const int pos = atomicAdd(&g_counts[e], 1);
    if (pos < CAP) {
        g_slot_tok[e * CAP + pos] = a / KK;
        g_slot_aid[e * CAP + pos] = a;
        g_valid[a] = 1;
    } else {
        g_valid[a] = 0;
    }
}

// ================= generic split-bf16 mma.sync GEMM =================
// CTA tile 128x128, K chunks of 32, 512 threads = 16 warps (4x4),
// warp tile 32x32. A: [128][40] bf16 hi/lo (row-major, padded).
// B: [32][136] bf16 hi/lo (K-major, padded) -> ldmatrix.trans.
//
// AMODE: 0 = gather rows of x via g_slot_tok (fp32, lda=K)
//        1 = dense fp32 A (x), lda=K
//        2 = pre-split bf16 A (g_h_* if GROUPED else g_sh*), lda=K
// EMODE: 0 = fp32 -> g_G[(e*CAP+s)*ID]            (routed gate)
//        4 = read g_G, swiglu, split -> g_h_hi/lo  (routed up)
//        1 = fp32 scatter by aid -> g_outa          (routed down)
//        2 = fp32 -> g_sG[t*ID]                     (shared gate)
//        5 = read g_sG, swiglu, split -> g_shh/l    (shared up)
//        3 = fp32 + routed combine -> Cf (out)      (shared down)

#define APAD 40
#define BPAD 136
#define STAGE_B (2 * 128 * APAD * 2 + 2 * 32 * BPAD * 2)   // 37888
#define OFF_AL  (128 * APAD * 2)                            // 10240
#define OFF_BH  (2 * 128 * APAD * 2)                        // 20480
#define OFF_BL  (OFF_BH + 32 * BPAD * 2)                    // 29184
#define GEMM_SMEM (2 * STAGE_B)                             // 75776

template<int AMODE, int EMODE, int GROUPED>
__global__ void __launch_bounds__(512, 1)
mma_gemm(const float* __restrict__ Af,
         const float* __restrict__ Bg, long long bstride, int ldb, int K,
         float* __restrict__ Cf, int ldc)
{
    const int e = GROUPED ? blockIdx.z : 0;
    const int cnt = GROUPED ? min(g_counts[e], CAP) : TT;
    const int m0 = blockIdx.y * 128;
    if (m0 >= cnt) return;
    const int n0 = blockIdx.x * 128;

    extern __shared__ char sm[];
    __shared__ int toks[128];
    __shared__ int aids[128];

    const int tid  = threadIdx.x;
    const int lane = tid & 31;
    const int wid  = tid >> 5;
    const int wm   = wid & 3;
    const int wn   = wid >> 2;

    if (tid < 128) {
        const int s = m0 + tid;
        if (AMODE == 0) toks[tid] = (s < cnt) ? g_slot_tok[e * CAP + s] : -1;
        if (EMODE == 1) aids[tid] = (s < cnt) ? g_slot_aid[e * CAP + s] : -1;
    }
    __syncthreads();

    // ---- A staging pointers ----
    const int arow = tid >> 2;            // 4 threads per row
    const int acs  = (tid & 3) * 8;       // col start (8 elems per thread)
    const float* aptr = nullptr;
    const __nv_bfloat16 *ahp = nullptr, *alp = nullptr;
    if (AMODE == 0) {
        const int tk = toks[arow];
        aptr = (tk >= 0) ? Af + (size_t)tk * K : nullptr;
    } else if (AMODE == 1) {
        aptr = Af + (size_t)(m0 + arow) * K;
    } else {
        const size_t r = (GROUPED ? (size_t)e * CAP : 0) + m0 + arow;
        if (GROUPED) { ahp = g_h_hi + r * K; alp = g_h_lo + r * K; }
        else         { ahp = g_shh  + r * K; alp = g_shl  + r * K; }
    }
    const float* Bp = Bg + (GROUPED ? (size_t)e * bstride : 0);

    // staging registers
    float arf[8];
    uint4 ahr, alr;
    float brf[8];

    auto LOAD_REGS = [&](int k0) {
        if (AMODE <= 1) {
            #pragma unroll
            for (int i = 0; i < 2; ++i) {
                float4 v = make_float4(0.f, 0.f, 0.f, 0.f);
                if (AMODE == 1 || aptr)
                    v = *reinterpret_cast<const float4*>(aptr + k0 + acs + i * 4);
                arf[i*4+0] = v.x; arf[i*4+1] = v.y; arf[i*4+2] = v.z; arf[i*4+3] = v.w;
            }
        } else {
            ahr = *reinterpret_cast<const uint4*>(ahp + k0 + acs);
            alr = *reinterpret_cast<const uint4*>(alp + k0 + acs);
        }
        #pragma unroll
        for (int i = 0; i < 2; ++i) {
            const int task = tid + 512 * i;      // 1024 tasks
            const int k  = task >> 5;
            const int nq = task & 31;
            const float4 v = *reinterpret_cast<const float4*>(
                Bp + (size_t)(k0 + k) * ldb + n0 + nq * 4);
            brf[i*4+0] = v.x; brf[i*4+1] = v.y; brf[i*4+2] = v.z; brf[i*4+3] = v.w;
        }
    };

    auto STORE_SM = [&](int buf) {
        char* st = sm + buf * STAGE_B;
        __nv_bfloat16* Ah = (__nv_bfloat16*)(st);
        __nv_bfloat16* Al = (__nv_bfloat16*)(st + OFF_AL);
        __nv_bfloat16* Bh = (__nv_bfloat16*)(st + OFF_BH);
        __nv_bfloat16* Bl = (__nv_bfloat16*)(st + OFF_BL);
        if (AMODE <= 1) {
            #pragma unroll
            for (int i = 0; i < 2; ++i) {
                unsigned short h[4], l[4];
                #pragma unroll
                for (int j = 0; j < 4; ++j) bsplit(arf[i*4+j], h[j], l[j]);
                *reinterpret_cast<uint2*>(&Ah[arow * APAD + acs + i*4]) =
                    make_uint2(pk(h[0], h[1]), pk(h[2], h[3]));
                *reinterpret_cast<uint2*>(&Al[arow * APAD + acs + i*4]) =
                    make_uint2(pk(l[0], l[1]), pk(l[2], l[3]));
            }
        } else {
            *reinterpret_cast<uint4*>(&Ah[arow * APAD + acs]) = ahr;
            *reinterpret_cast<uint4*>(&Al[arow * APAD + acs]) = alr;
        }
        #pragma unroll
        for (int i = 0; i < 2; ++i) {
            const int task = tid + 512 * i;
            const int k  = task >> 5;
            const int nq = task & 31;
            unsigned short h[4], l[4];
            #pragma unroll
            for (int j = 0; j < 4; ++j) bsplit(brf[i*4+j], h[j], l[j]);
            *reinterpret_cast<uint2*>(&Bh[k * BPAD + nq*4]) =
                make_uint2(pk(h[0], h[1]), pk(h[2], h[3]));
            *reinterpret_cast<uint2*>(&Bl[k * BPAD + nq*4]) =
                make_uint2(pk(l[0], l[1]), pk(l[2], l[3]));
        }
    };

    // per-lane ldmatrix address components
    const uint32_t smb = smem_u32(sm);
    const int a_row16  = (lane & 7) + ((lane >> 3) & 1) * 8;  // row within m16
    const int a_khalf  = lane >> 4;                           // 0/1 -> +8 elems
    const int b_k      = (lane & 7) + ((lane >> 3) & 1) * 8;  // k within k16
    const int b_nhalf  = (lane >> 4) & 1;                     // 0/1 -> +8 cols

    float acc[2][4][4];
    #pragma unroll
    for (int a = 0; a < 2; ++a)
        #pragma unroll
        for (int b = 0; b < 4; ++b)
            #pragma unroll
            for (int c = 0; c < 4; ++c) acc[a][b][c] = 0.f;

    const int NCH = K / 32;
    LOAD_REGS(0);
    STORE_SM(0);
    __syncthreads();

    for (int ch = 0; ch < NCH; ++ch) {
        const int buf = ch & 1;
        if (ch + 1 < NCH) LOAD_REGS((ch + 1) * 32);

        const uint32_t stb = smb + buf * STAGE_B;
        #pragma unroll
        for (int ks = 0; ks < 2; ++ks) {
            uint32_t ah[2][4], al[2][4];
            #pragma unroll
            for (int mt = 0; mt < 2; ++mt) {
                const uint32_t aoff =
                    (uint32_t)((wm*32 + mt*16 + a_row16) * (APAD*2) + ks*32 + a_khalf*16);
                ldsm4(ah[mt], stb + aoff);
                ldsm4(al[mt], stb + OFF_AL + aoff);
            }
            #pragma unroll
            for (int ntp = 0; ntp < 2; ++ntp) {
                uint32_t bh[4], bl[4];
                const uint32_t boff =
                    (uint32_t)((ks*16 + b_k) * (BPAD*2) +
                               (wn*32 + ntp*16 + b_nhalf*8) * 2);
                ldsm4t(bh, stb + OFF_BH + boff);
                ldsm4t(bl, stb + OFF_BL + boff);
                #pragma unroll
                for (int half = 0; half < 2; ++half) {
                    const int nt = ntp*2 + half;
                    const uint32_t b0h = bh[half*2], b1h = bh[half*2+1];
                    const uint32_t b0l = bl[half*2], b1l = bl[half*2+1];
                    #pragma unroll
                    for (int mt = 0; mt < 2; ++mt) {
                        mma16816(acc[mt][nt], ah[mt], b0h, b1h);
                        mma16816(acc[mt][nt], ah[mt], b0l, b1l);
                        mma16816(acc[mt][nt], al[mt], b0h, b1h);
                    }
                }
            }
        }
        __syncthreads();
        if (ch + 1 < NCH) { STORE_SM(buf ^ 1); __syncthreads(); }
    }

    // ---- epilogue ----
    const int r0 = lane >> 2;
    const int c0 = (lane & 3) * 2;

    #pragma unroll
    for (int mt = 0; mt < 2; ++mt) {
        #pragma unroll
        for (int rr = 0; rr < 2; ++rr) {
            const int lrow = wm*32 + mt*16 + r0 + rr*8;   // local row 0..127
            const int s    = m0 + lrow;
            if (GROUPED && s >= cnt) continue;

            if (EMODE == 3) {
                // shared down + combine
                float w[KK]; int vd[KK];
                #pragma unroll
                for (int k = 0; k < KK; ++k) {
                    const int a = s * KK + k;
                    vd[k] = g_valid[a];
                    w[k]  = g_topk_w[a];
                }
                #pragma unroll
                for (int nt = 0; nt < 4; ++nt) {
                    const int col = n0 + wn*32 + nt*8 + c0;
                    float o0 = acc[mt][nt][rr*2], o1 = acc[mt][nt][rr*2+1];
                    #pragma unroll
                    for (int k = 0; k < KK; ++k) {
                        if (vd[k]) {
                            const float2 v = *reinterpret_cast<const float2*>(
                                g_outa + (size_t)(s*KK + k) * HD + col);
                            o0 = fmaf(w[k], v.x, o0);
                            o1 = fmaf(w[k], v.y, o1);
                        }
                    }
                    *reinterpret_cast<float2*>(Cf + (size_t)s * ldc + col) =
                        make_float2(o0, o1);
                }
            } else if (EMODE == 1) {
                const int aid = aids[lrow];
                if (aid < 0) continue;
                #pragma unroll
                for (int nt = 0; nt < 4; ++nt) {
                    const int col = n0 + wn*32 + nt*8 + c0;
                    *reinterpret_cast<float2*>(g_outa + (size_t)aid * HD + col) =
                        make_float2(acc[mt][nt][rr*2], acc[mt][nt][rr*2+1]);
                }
            } else if (EMODE == 0 || EMODE == 2) {
                float* base = (EMODE == 0)
                    ? g_G + ((size_t)e * CAP + s) * ldc
                    : g_sG + (size_t)s * ldc;
                #pragma unroll
                for (int nt = 0; nt < 4; ++nt) {
                    const int col = n0 + wn*32 + nt*8 + c0;
                    *reinterpret_cast<float2*>(base + col) =
                        make_float2(acc[mt][nt][rr*2], acc[mt][nt][rr*2+1]);
                }
            } else {
                // EMODE 4/5: fused swiglu + split
                const size_t ridx = (EMODE == 4) ? ((size_t)e * CAP + s) * ID
                                                 : (size_t)s * ID;
                const float* gsrc = (EMODE == 4) ? g_G : g_sG;
                __nv_bfloat16* hh = (EMODE == 4) ? g_h_hi : g_shh;
                __nv_bfloat16* hl = (EMODE == 4) ? g_h_lo : g_shl;
                #pragma unroll
                for (int nt = 0; nt < 4; ++nt) {
                    const int col = n0 + wn*32 + nt*8 + c0;
                    const float2 g = *reinterpret_cast<const float2*>(gsrc + ridx + col);
                    const float h0 = silu(g.x) * acc[mt][nt][rr*2];
                    const float h1 = silu(g.y) * acc[mt][nt][rr*2+1];
                    unsigned short hh0, ll0, hh1, ll1;
                    bsplit(h0, hh0, ll0);
                    bsplit(h1, hh1, ll1);
                    *reinterpret_cast<uint32_t*>(hh + ridx + col) = pk(hh0, hh1);
                    *reinterpret_cast<uint32_t*>(hl + ridx + col) = pk(ll0, ll1);
                }
            }
        }
    }
}

// ---------------- launch ----------------
extern "C" void kernel_launch(void* const* d_in, const int* in_sizes, int n_in,
                              void* d_out, int out_size)
{
    const float* x   = (const float*)d_in[0];
    const float* rw  = (const float*)d_in[1];
    const float* gw  = (const float*)d_in[2];
    const float* uw  = (const float*)d_in[3];
    const float* dw  = (const float*)d_in[4];
    const float* sgw = (const float*)d_in[5];
    const float* suw = (const float*)d_in[6];
    const float* sdw = (const float*)d_in[7];
    float* out = (float*)d_out;

    cudaFuncSetAttribute(mma_gemm<0,0,1>, cudaFuncAttributeMaxDynamicSharedMemorySize, GEMM_SMEM);
    cudaFuncSetAttribute(mma_gemm<0,4,1>, cudaFuncAttributeMaxDynamicSharedMemorySize, GEMM_SMEM);
    cudaFuncSetAttribute(mma_gemm<2,1,1>, cudaFuncAttributeMaxDynamicSharedMemorySize, GEMM_SMEM);
    cudaFuncSetAttribute(mma_gemm<1,2,0>, cudaFuncAttributeMaxDynamicSharedMemorySize, GEMM_SMEM);
    cudaFuncSetAttribute(mma_gemm<1,5,0>, cudaFuncAttributeMaxDynamicSharedMemorySize, GEMM_SMEM);
    cudaFuncSetAttribute(mma_gemm<2,3,0>, cudaFuncAttributeMaxDynamicSharedMemorySize, GEMM_SMEM);

    router_kernel<<<TT, 64>>>(x, rw);
    zero_counts_kernel<<<1, 64>>>();
    assign_kernel<<<(TT * KK + 255) / 256, 256>>>();

    // routed experts
    mma_gemm<0,0,1><<<dim3(ID/128, CAP/128, NE), 512, GEMM_SMEM>>>(
        x, gw, (long long)HD * ID, ID, HD, nullptr, ID);
    mma_gemm<0,4,1><<<dim3(ID/128, CAP/128, NE), 512, GEMM_SMEM>>>(
        x, uw, (long long)HD * ID, ID, HD, nullptr, ID);
    mma_gemm<2,1,1><<<dim3(HD/128, CAP/128, NE), 512, GEMM_SMEM>>>(
        nullptr, dw, (long long)ID * HD, HD, ID, nullptr, HD);

    // shared expert
    mma_gemm<1,2,0><<<dim3(ID/128, TT/128, 1), 512, GEMM_SMEM>>>(
        x, sgw, 0, ID, HD, nullptr, ID);
    mma_gemm<1,5,0><<<dim3(ID/128, TT/128, 1), 512, GEMM_SMEM>>>(
        x, suw, 0, ID, HD, nullptr, ID);
    mma_gemm<2,3,0><<<dim3(HD/128, TT/128, 1), 512, GEMM_SMEM>>>(
        nullptr, sdw, 0, HD, ID, out, HD);
}

// round 8
// speedup vs baseline: 1.0027x; 1.0027x over previous
#include <cuda_runtime.h>
#include <cuda_bf16.h>
#include <math.h>
#include <stdint.h>

// ---------------- problem constants ----------------
#define TT   1024
#define HD   1024
#define NE   64
#define ID   512
#define KK   8
#define NG   8
#define TG   4
#define EG   8
#define CAP  512
#define RSCALE 2.5f

// ---------------- device scratch ----------------
__device__ int   g_topk_idx[TT * KK];
__device__ float g_topk_w[TT * KK];
__device__ int   g_counts[NE];
__device__ int   g_slot_tok[NE * CAP];
__device__ int   g_slot_aid[NE * CAP];
__device__ int   g_valid[TT * KK];
__device__ float g_G[(size_t)NE * CAP * ID];              // gate GEMM out (fp32)
__device__ __nv_bfloat16 g_h_hi[(size_t)NE * CAP * ID];   // swiglu hi
__device__ __nv_bfloat16 g_h_lo[(size_t)NE * CAP * ID];   // swiglu lo
__device__ float g_outa[(size_t)TT * KK * HD];            // per-assignment down out
__device__ float g_sG[(size_t)TT * ID];                   // shared gate out (fp32)
__device__ __nv_bfloat16 g_shh[(size_t)TT * ID];          // shared hidden hi
__device__ __nv_bfloat16 g_shl[(size_t)TT * ID];          // shared hidden lo

// ---------------- helpers ----------------
__device__ __forceinline__ uint32_t smem_u32(const void* p) {
    uint32_t a;
    asm("{ .reg .u64 t; cvta.to.shared.u64 t, %1; cvt.u32.u64 %0, t; }"
        : "=r"(a) : "l"(p));
    return a;
}

__device__ __forceinline__ void bsplit(float a, unsigned short& h, unsigned short& l) {
    __nv_bfloat16 hb = __float2bfloat16(a);
    __nv_bfloat16 lb = __float2bfloat16(a - __bfloat162float(hb));
    h = __bfloat16_as_ushort(hb);
    l = __bfloat16_as_ushort(lb);
}
__device__ __forceinline__ uint32_t pk(unsigned short a, unsigned short b) {
    return (uint32_t)a | ((uint32_t)b << 16);
}

__device__ __forceinline__ void ldsm4(uint32_t* r, uint32_t addr) {
    asm volatile("ldmatrix.sync.aligned.m8n8.x4.shared.b16 {%0,%1,%2,%3}, [%4];"
        : "=r"(r[0]), "=r"(r[1]), "=r"(r[2]), "=r"(r[3]) : "r"(addr));
}
__device__ __forceinline__ void ldsm4t(uint32_t* r, uint32_t addr) {
    asm volatile("ldmatrix.sync.aligned.m8n8.x4.trans.shared.b16 {%0,%1,%2,%3}, [%4];"
        : "=r"(r[0]), "=r"(r[1]), "=r"(r[2]), "=r"(r[3]) : "r"(addr));
}
__device__ __forceinline__ void mma16816(float* d, const uint32_t* a,
                                         uint32_t b0, uint32_t b1) {
    asm volatile(
        "mma.sync.aligned.m16n8k16.row.col.f32.bf16.bf16.f32 "
        "{%0,%1,%2,%3}, {%4,%5,%6,%7}, {%8,%9}, {%0,%1,%2,%3};"
        : "+f"(d[0]), "+f"(d[1]), "+f"(d[2]), "+f"(d[3])
        : "r"(a[0]), "r"(a[1]), "r"(a[2]), "r"(a[3]), "r"(b0), "r"(b1));
}

__device__ __forceinline__ float silu(float g) { return g / (1.f + expf(-g)); }

// ---------------- router ----------------
__global__ void router_kernel(const float* __restrict__ x,
                              const float* __restrict__ rw)
{
    const int t = blockIdx.x;
    __shared__ float xs[HD];
    __shared__ float sc[NE];
    __shared__ float ms[NE];
    __shared__ float gm[NG];
    __shared__ int   selg[NG];

    for (int i = threadIdx.x; i < HD; i += blockDim.x)
        xs[i] = x[(size_t)t * HD + i];
    __syncthreads();

    const int e = threadIdx.x;
    if (e < NE) {
        float acc = 0.f;
        #pragma unroll 8
        for (int h = 0; h < HD; ++h)
            acc = fmaf(xs[h], rw[(size_t)h * NE + e], acc);
        sc[e] = 1.f / (1.f + expf(-acc));
    }
    __syncthreads();

    if (threadIdx.x == 0) {
        for (int g = 0; g < NG; ++g) {
            float m = sc[g * EG];
            for (int j = 1; j < EG; ++j) m = fmaxf(m, sc[g * EG + j]);
            gm[g] = m; selg[g] = 0;
        }
        for (int r = 0; r < TG; ++r) {
            int bi = -1; float bv = -1e30f;
            for (int g = 0; g < NG; ++g)
                if (!selg[g] && gm[g] > bv) { bv = gm[g]; bi = g; }
            selg[bi] = 1;
        }
        for (int ee = 0; ee < NE; ++ee)
            ms[ee] = selg[ee / EG] ? sc[ee] : 0.0f;

        int   idx[KK];
        float val[KK];
        float sum = 0.f;
        for (int r = 0; r < KK; ++r) {
            int bi = 0; float bv = ms[0];
            for (int ee = 1; ee < NE; ++ee)
                if (ms[ee] > bv) { bv = ms[ee]; bi = ee; }
            idx[r] = bi; val[r] = bv; ms[bi] = -1.f; sum += bv;
        }
        const float inv = RSCALE / fmaxf(sum, 1e-9f);
        for (int r = 0; r < KK; ++r) {
            g_topk_idx[t * KK + r] = idx[r];
            g_topk_w[t * KK + r]   = val[r] * inv;
        }
    }
}

__global__ void zero_counts_kernel()
{
    if (threadIdx.x < NE) g_counts[threadIdx.x] = 0;
}

__global__ void assign_kernel()
{
    const int a = blockIdx.x * blockDim.x + threadIdx.x;
    if (a >= TT * KK) return;
    const int e = g_topk_idx[a];
    const int pos = atomicAdd(&g_counts[e], 1);
    if (pos < CAP) {
        g_slot_tok[e * CAP + pos] = a / KK;
        g_slot_aid[e * CAP + pos] = a;
        g_valid[a] = 1;
    } else {
        g_valid[a] = 0;
    }
}

// ================= generic split-bf16 mma.sync GEMM =================
// CTA tile 128x128, K chunks of 32, 512 threads = 16 warps (4x4),
// warp tile 32x32. A: [128][40] bf16 hi/lo (row-major, padded).
// B: [32][136] bf16 hi/lo (K-major, padded) -> ldmatrix.trans.
//
// AMODE: 0 = gather rows of x via g_slot_tok (fp32, lda=K)
//        1 = dense fp32 A (x), lda=K
//        2 = pre-split bf16 A (g_h_* if GROUPED else g_sh*), lda=K
// EMODE: 0 = fp32 -> g_G[(e*CAP+s)*ID]            (routed gate)
//        4 = read g_G, swiglu, split -> g_h_hi/lo  (routed up)
//        1 = fp32 scatter by aid -> g_outa          (routed down)
//        2 = fp32 -> g_sG[t*ID]                     (shared gate)
//        5 = read g_sG, swiglu, split -> g_shh/l    (shared up)
//        3 = fp32 + routed combine -> Cf (out)      (shared down)

#define APAD 40
#define BPAD 136
#define STAGE_B (2 * 128 * APAD * 2 + 2 * 32 * BPAD * 2)   // 37888
#define OFF_AL  (128 * APAD * 2)                            // 10240
#define OFF_BH  (2 * 128 * APAD * 2)                        // 20480
#define OFF_BL  (OFF_BH + 32 * BPAD * 2)                    // 29184
#define GEMM_SMEM (2 * STAGE_B)                             // 75776

template<int AMODE, int EMODE, int GROUPED>
__global__ void __launch_bounds__(512, 1)
mma_gemm(const float* __restrict__ Af,
         const float* __restrict__ Bg, long long bstride, int ldb, int K,
         float* __restrict__ Cf, int ldc)
{
    const int e = GROUPED ? blockIdx.z : 0;
    const int cnt = GROUPED ? min(g_counts[e], CAP) : TT;
    const int m0 = blockIdx.y * 128;
    if (m0 >= cnt) return;
    const int n0 = blockIdx.x * 128;

    extern __shared__ char sm[];
    __shared__ int toks[128];
    __shared__ int aids[128];

    const int tid  = threadIdx.x;
    const int lane = tid & 31;
    const int wid  = tid >> 5;
    const int wm   = wid & 3;
    const int wn   = wid >> 2;

    if (tid < 128) {
        const int s = m0 + tid;
        if (AMODE == 0) toks[tid] = (s < cnt) ? g_slot_tok[e * CAP + s] : -1;
        if (EMODE == 1) aids[tid] = (s < cnt) ? g_slot_aid[e * CAP + s] : -1;
    }
    __syncthreads();

    // ---- A staging pointers ----
    const int arow = tid >> 2;            // 4 threads per row
    const int acs  = (tid & 3) * 8;       // col start (8 elems per thread)
    const float* aptr = nullptr;
    const __nv_bfloat16 *ahp = nullptr, *alp = nullptr;
    if (AMODE == 0) {
        const int tk = toks[arow];
        aptr = (tk >= 0) ? Af + (size_t)tk * K : nullptr;
    } else if (AMODE == 1) {
        aptr = Af + (size_t)(m0 + arow) * K;
    } else {
        const size_t r = (GROUPED ? (size_t)e * CAP : 0) + m0 + arow;
        if (GROUPED) { ahp = g_h_hi + r * K; alp = g_h_lo + r * K; }
        else         { ahp = g_shh  + r * K; alp = g_shl  + r * K; }
    }
    const float* Bp = Bg + (GROUPED ? (size_t)e * bstride : 0);

    // staging registers
    float arf[8];
    uint4 ahr, alr;
    float brf[8];

    auto LOAD_REGS = [&](int k0) {
        if (AMODE <= 1) {
            #pragma unroll
            for (int i = 0; i < 2; ++i) {
                float4 v = make_float4(0.f, 0.f, 0.f, 0.f);
                if (AMODE == 1 || aptr)
                    v = *reinterpret_cast<const float4*>(aptr + k0 + acs + i * 4);
                arf[i*4+0] = v.x; arf[i*4+1] = v.y; arf[i*4+2] = v.z; arf[i*4+3] = v.w;
            }
        } else {
            ahr = *reinterpret_cast<const uint4*>(ahp + k0 + acs);
            alr = *reinterpret_cast<const uint4*>(alp + k0 + acs);
        }
        #pragma unroll
        for (int i = 0; i < 2; ++i) {
            const int task = tid + 512 * i;      // 1024 tasks
            const int k  = task >> 5;
            const int nq = task & 31;
            const float4 v = *reinterpret_cast<const float4*>(
                Bp + (size_t)(k0 + k) * ldb + n0 + nq * 4);
            brf[i*4+0] = v.x; brf[i*4+1] = v.y; brf[i*4+2] = v.z; brf[i*4+3] = v.w;
        }
    };

    auto STORE_SM = [&](int buf) {
        char* st = sm + buf * STAGE_B;
        __nv_bfloat16* Ah = (__nv_bfloat16*)(st);
        __nv_bfloat16* Al = (__nv_bfloat16*)(st + OFF_AL);
        __nv_bfloat16* Bh = (__nv_bfloat16*)(st + OFF_BH);
        __nv_bfloat16* Bl = (__nv_bfloat16*)(st + OFF_BL);
        if (AMODE <= 1) {
            #pragma unroll
            for (int i = 0; i < 2; ++i) {
                unsigned short h[4], l[4];
                #pragma unroll
                for (int j = 0; j < 4; ++j) bsplit(arf[i*4+j], h[j], l[j]);
                *reinterpret_cast<uint2*>(&Ah[arow * APAD + acs + i*4]) =
                    make_uint2(pk(h[0], h[1]), pk(h[2], h[3]));
                *reinterpret_cast<uint2*>(&Al[arow * APAD + acs + i*4]) =
                    make_uint2(pk(l[0], l[1]), pk(l[2], l[3]));
            }
        } else {
            *reinterpret_cast<uint4*>(&Ah[arow * APAD + acs]) = ahr;
            *reinterpret_cast<uint4*>(&Al[arow * APAD + acs]) = alr;
        }
        #pragma unroll
        for (int i = 0; i < 2; ++i) {
            const int task = tid + 512 * i;
            const int k  = task >> 5;
            const int nq = task & 31;
            unsigned short h[4], l[4];
            #pragma unroll
            for (int j = 0; j < 4; ++j) bsplit(brf[i*4+j], h[j], l[j]);
            *reinterpret_cast<uint2*>(&Bh[k * BPAD + nq*4]) =
                make_uint2(pk(h[0], h[1]), pk(h[2], h[3]));
            *reinterpret_cast<uint2*>(&Bl[k * BPAD + nq*4]) =
                make_uint2(pk(l[0], l[1]), pk(l[2], l[3]));
        }
    };

    // per-lane ldmatrix address components
    const uint32_t smb = smem_u32(sm);
    const int a_row16  = (lane & 7) + ((lane >> 3) & 1) * 8;  // row within m16
    const int a_khalf  = lane >> 4;                           // 0/1 -> +8 elems
    const int b_k      = (lane & 7) + ((lane >> 3) & 1) * 8;  // k within k16
    const int b_nhalf  = (lane >> 4) & 1;                     // 0/1 -> +8 cols

    float acc[2][4][4];
    #pragma unroll
    for (int a = 0; a < 2; ++a)
        #pragma unroll
        for (int b = 0; b < 4; ++b)
            #pragma unroll
            for (int c = 0; c < 4; ++c) acc[a][b][c] = 0.f;

    const int NCH = K / 32;
    LOAD_REGS(0);
    STORE_SM(0);
    __syncthreads();

    for (int ch = 0; ch < NCH; ++ch) {
        const int buf = ch & 1;
        if (ch + 1 < NCH) LOAD_REGS((ch + 1) * 32);

        const uint32_t stb = smb + buf * STAGE_B;
        #pragma unroll
        for (int ks = 0; ks < 2; ++ks) {
            uint32_t ah[2][4], al[2][4];
            #pragma unroll
            for (int mt = 0; mt < 2; ++mt) {
                const uint32_t aoff =
                    (uint32_t)((wm*32 + mt*16 + a_row16) * (APAD*2) + ks*32 + a_khalf*16);
                ldsm4(ah[mt], stb + aoff);
                ldsm4(al[mt], stb + OFF_AL + aoff);
            }
            #pragma unroll
            for (int ntp = 0; ntp < 2; ++ntp) {
                uint32_t bh[4], bl[4];
                const uint32_t boff =
                    (uint32_t)((ks*16 + b_k) * (BPAD*2) +
                               (wn*32 + ntp*16 + b_nhalf*8) * 2);
                ldsm4t(bh, stb + OFF_BH + boff);
                ldsm4t(bl, stb + OFF_BL + boff);
                #pragma unroll
                for (int half = 0; half < 2; ++half) {
                    const int nt = ntp*2 + half;
                    const uint32_t b0h = bh[half*2], b1h = bh[half*2+1];
                    const uint32_t b0l = bl[half*2], b1l = bl[half*2+1];
                    #pragma unroll
                    for (int mt = 0; mt < 2; ++mt) {
                        mma16816(acc[mt][nt], ah[mt], b0h, b1h);
                        mma16816(acc[mt][nt], ah[mt], b0l, b1l);
                        mma16816(acc[mt][nt], al[mt], b0h, b1h);
                    }
                }
            }
        }
        __syncthreads();
        if (ch + 1 < NCH) { STORE_SM(buf ^ 1); __syncthreads(); }
    }

    // ---- epilogue ----
    const int r0 = lane >> 2;
    const int c0 = (lane & 3) * 2;

    #pragma unroll
    for (int mt = 0; mt < 2; ++mt) {
        #pragma unroll
        for (int rr = 0; rr < 2; ++rr) {
            const int lrow = wm*32 + mt*16 + r0 + rr*8;   // local row 0..127
            const int s    = m0 + lrow;
            if (GROUPED && s >= cnt) continue;

            if (EMODE == 3) {
                // shared down + combine
                float w[KK]; int vd[KK];
                #pragma unroll
                for (int k = 0; k < KK; ++k) {
                    const int a = s * KK + k;
                    vd[k] = g_valid[a];
                    w[k]  = g_topk_w[a];
                }
                #pragma unroll
                for (int nt = 0; nt < 4; ++nt) {
                    const int col = n0 + wn*32 + nt*8 + c0;
                    float o0 = acc[mt][nt][rr*2], o1 = acc[mt][nt][rr*2+1];
                    #pragma unroll
                    for (int k = 0; k < KK; ++k) {
                        if (vd[k]) {
                            const float2 v = *reinterpret_cast<const float2*>(
                                g_outa + (size_t)(s*KK + k) * HD + col);
                            o0 = fmaf(w[k], v.x, o0);
                            o1 = fmaf(w[k], v.y, o1);
                        }
                    }
                    *reinterpret_cast<float2*>(Cf + (size_t)s * ldc + col) =
                        make_float2(o0, o1);
                }
            } else if (EMODE == 1) {
                const int aid = aids[lrow];
                if (aid < 0) continue;
                #pragma unroll
                for (int nt = 0; nt < 4; ++nt) {
                    const int col = n0 + wn*32 + nt*8 + c0;
                    *reinterpret_cast<float2*>(g_outa + (size_t)aid * HD + col) =
                        make_float2(acc[mt][nt][rr*2], acc[mt][nt][rr*2+1]);
                }
            } else if (EMODE == 0 || EMODE == 2) {
                float* base = (EMODE == 0)
                    ? g_G + ((size_t)e * CAP + s) * ldc
                    : g_sG + (size_t)s * ldc;
                #pragma unroll
                for (int nt = 0; nt < 4; ++nt) {
                    const int col = n0 + wn*32 + nt*8 + c0;
                    *reinterpret_cast<float2*>(base + col) =
                        make_float2(acc[mt][nt][rr*2], acc[mt][nt][rr*2+1]);
                }
            } else {
                // EMODE 4/5: fused swiglu + split
                const size_t ridx = (EMODE == 4) ? ((size_t)e * CAP + s) * ID
                                                 : (size_t)s * ID;
                const float* gsrc = (EMODE == 4) ? g_G : g_sG;
                __nv_bfloat16* hh = (EMODE == 4) ? g_h_hi : g_shh;
                __nv_bfloat16* hl = (EMODE == 4) ? g_h_lo : g_shl;
                #pragma unroll
                for (int nt = 0; nt < 4; ++nt) {
                    const int col = n0 + wn*32 + nt*8 + c0;
                    const float2 g = *reinterpret_cast<const float2*>(gsrc + ridx + col);
                    const float h0 = silu(g.x) * acc[mt][nt][rr*2];
                    const float h1 = silu(g.y) * acc[mt][nt][rr*2+1];
                    unsigned short hh0, ll0, hh1, ll1;
                    bsplit(h0, hh0, ll0);
                    bsplit(h1, hh1, ll1);
                    *reinterpret_cast<uint32_t*>(hh + ridx + col) = pk(hh0, hh1);
                    *reinterpret_cast<uint32_t*>(hl + ridx + col) = pk(ll0, ll1);
                }
            }
        }
    }
}

// ---------------- launch ----------------
extern "C" void kernel_launch(void* const* d_in, const int* in_sizes, int n_in,
                              void* d_out, int out_size)
{
    const float* x   = (const float*)d_in[0];
    const float* rw  = (const float*)d_in[1];
    const float* gw  = (const float*)d_in[2];
    const float* uw  = (const float*)d_in[3];
    const float* dw  = (const float*)d_in[4];
    const float* sgw = (const float*)d_in[5];
    const float* suw = (const float*)d_in[6];
    const float* sdw = (const float*)d_in[7];
    float* out = (float*)d_out;

    cudaFuncSetAttribute(mma_gemm<0,0,1>, cudaFuncAttributeMaxDynamicSharedMemorySize, GEMM_SMEM);
    cudaFuncSetAttribute(mma_gemm<0,4,1>, cudaFuncAttributeMaxDynamicSharedMemorySize, GEMM_SMEM);
    cudaFuncSetAttribute(mma_gemm<2,1,1>, cudaFuncAttributeMaxDynamicSharedMemorySize, GEMM_SMEM);
    cudaFuncSetAttribute(mma_gemm<1,2,0>, cudaFuncAttributeMaxDynamicSharedMemorySize, GEMM_SMEM);
    cudaFuncSetAttribute(mma_gemm<1,5,0>, cudaFuncAttributeMaxDynamicSharedMemorySize, GEMM_SMEM);
    cudaFuncSetAttribute(mma_gemm<2,3,0>, cudaFuncAttributeMaxDynamicSharedMemorySize, GEMM_SMEM);

    router_kernel<<<TT, 64>>>(x, rw);
    zero_counts_kernel<<<1, 64>>>();
    assign_kernel<<<(TT * KK + 255) / 256, 256>>>();

    // routed experts
    mma_gemm<0,0,1><<<dim3(ID/128, CAP/128, NE), 512, GEMM_SMEM>>>(
        x, gw, (long long)HD * ID, ID, HD, nullptr, ID);
    mma_gemm<0,4,1><<<dim3(ID/128, CAP/128, NE), 512, GEMM_SMEM>>>(
        x, uw, (long long)HD * ID, ID, HD, nullptr, ID);
    mma_gemm<2,1,1><<<dim3(HD/128, CAP/128, NE), 512, GEMM_SMEM>>>(
        nullptr, dw, (long long)ID * HD, HD, ID, nullptr, HD);

    // shared expert
    mma_gemm<1,2,0><<<dim3(ID/128, TT/128, 1), 512, GEMM_SMEM>>>(
        x, sgw, 0, ID, HD, nullptr, ID);
    mma_gemm<1,5,0><<<dim3(ID/128, TT/128, 1), 512, GEMM_SMEM>>>(
        x, suw, 0, ID, HD, nullptr, ID);
    mma_gemm<2,3,0><<<dim3(HD/128, TT/128, 1), 512, GEMM_SMEM>>>(
        nullptr, sdw, 0, HD, ID, out, HD);
}

// round 9
// speedup vs baseline: 1.0035x; 1.0008x over previous
#include <cuda_runtime.h>
#include <cuda_bf16.h>
#include <math.h>
#include <stdint.h>

// ---------------- problem constants ----------------
#define TT   1024
#define HD   1024
#define NE   64
#define ID   512
#define KK   8
#define NG   8
#define TG   4
#define EG   8
#define CAP  512
#define RSCALE 2.5f

// ---------------- device scratch ----------------
__device__ int   g_topk_idx[TT * KK];
__device__ float g_topk_w[TT * KK];
__device__ int   g_counts[NE];
__device__ int   g_slot_tok[NE * CAP];
__device__ int   g_slot_aid[NE * CAP];
__device__ int   g_valid[TT * KK];
__device__ float g_G[(size_t)NE * CAP * ID];              // gate GEMM out (fp32)
__device__ __nv_bfloat16 g_h_hi[(size_t)NE * CAP * ID];   // swiglu hi
__device__ __nv_bfloat16 g_h_lo[(size_t)NE * CAP * ID];   // swiglu lo
__device__ float g_outa[(size_t)TT * KK * HD];            // per-assignment down out
__device__ float g_sG[(size_t)TT * ID];                   // shared gate out (fp32)
__device__ __nv_bfloat16 g_shh[(size_t)TT * ID];          // shared hidden hi
__device__ __nv_bfloat16 g_shl[(size_t)TT * ID];          // shared hidden lo

// ---------------- helpers ----------------
__device__ __forceinline__ uint32_t smem_u32(const void* p) {
    uint32_t a;
    asm("{ .reg .u64 t; cvta.to.shared.u64 t, %1; cvt.u32.u64 %0, t; }"
        : "=r"(a) : "l"(p));
    return a;
}

__device__ __forceinline__ void bsplit(float a, unsigned short& h, unsigned short& l) {
    __nv_bfloat16 hb = __float2bfloat16(a);
    __nv_bfloat16 lb = __float2bfloat16(a - __bfloat162float(hb));
    h = __bfloat16_as_ushort(hb);
    l = __bfloat16_as_ushort(lb);
}
__device__ __forceinline__ uint32_t pk(unsigned short a, unsigned short b) {
    return (uint32_t)a | ((uint32_t)b << 16);
}

__device__ __forceinline__ void ldsm4(uint32_t* r, uint32_t addr) {
    asm volatile("ldmatrix.sync.aligned.m8n8.x4.shared.b16 {%0,%1,%2,%3}, [%4];"
        : "=r"(r[0]), "=r"(r[1]), "=r"(r[2]), "=r"(r[3]) : "r"(addr));
}
__device__ __forceinline__ void ldsm4t(uint32_t* r, uint32_t addr) {
    asm volatile("ldmatrix.sync.aligned.m8n8.x4.trans.shared.b16 {%0,%1,%2,%3}, [%4];"
        : "=r"(r[0]), "=r"(r[1]), "=r"(r[2]), "=r"(r[3]) : "r"(addr));
}
__device__ __forceinline__ void mma16816(float* d, const uint32_t* a,
                                         uint32_t b0, uint32_t b1) {
    asm volatile(
        "mma.sync.aligned.m16n8k16.row.col.f32.bf16.bf16.f32 "
        "{%0,%1,%2,%3}, {%4,%5,%6,%7}, {%8,%9}, {%0,%1,%2,%3};"
        : "+f"(d[0]), "+f"(d[1]), "+f"(d[2]), "+f"(d[3])
        : "r"(a[0]), "r"(a[1]), "r"(a[2]), "r"(a[3]), "r"(b0), "r"(b1));
}

__device__ __forceinline__ float silu(float g) { return g / (1.f + expf(-g)); }

// ---------------- router ----------------
__global__ void router_kernel(const float* __restrict__ x,
                              const float* __restrict__ rw)
{
    const int t = blockIdx.x;
    __shared__ float xs[HD];
    __shared__ float sc[NE];
    __shared__ float ms[NE];
    __shared__ float gm[NG];
    __shared__ int   selg[NG];

    for (int i = threadIdx.x; i < HD; i += blockDim.x)
        xs[i] = x[(size_t)t * HD + i];
    __syncthreads();

    const int e = threadIdx.x;
    if (e < NE) {
        float acc = 0.f;
        #pragma unroll 8
        for (int h = 0; h < HD; ++h)
            acc = fmaf(xs[h], rw[(size_t)h * NE + e], acc);
        sc[e] = 1.f / (1.f + expf(-acc));
    }
    __syncthreads();

    if (threadIdx.x == 0) {
        for (int g = 0; g < NG; ++g) {
            float m = sc[g * EG];
            for (int j = 1; j < EG; ++j) m = fmaxf(m, sc[g * EG + j]);
            gm[g] = m; selg[g] = 0;
        }
        for (int r = 0; r < TG; ++r) {
            int bi = -1; float bv = -1e30f;
            for (int g = 0; g < NG; ++g)
                if (!selg[g] && gm[g] > bv) { bv = gm[g]; bi = g; }
            selg[bi] = 1;
        }
        for (int ee = 0; ee < NE; ++ee)
            ms[ee] = selg[ee / EG] ? sc[ee] : 0.0f;

        int   idx[KK];
        float val[KK];
        float sum = 0.f;
        for (int r = 0; r < KK; ++r) {
            int bi = 0; float bv = ms[0];
            for (int ee = 1; ee < NE; ++ee)
                if (ms[ee] > bv) { bv = ms[ee]; bi = ee; }
            idx[r] = bi; val[r] = bv; ms[bi] = -1.f; sum += bv;
        }
        const float inv = RSCALE / fmaxf(sum, 1e-9f);
        for (int r = 0; r < KK; ++r) {
            g_topk_idx[t * KK + r] = idx[r];
            g_topk_w[t * KK + r]   = val[r] * inv;
        }
    }
}

__global__ void zero_counts_kernel()
{
    if (threadIdx.x < NE) g_counts[threadIdx.x] = 0;
}

__global__ void assign_kernel()
{
    const int a = blockIdx.x * blockDim.x + threadIdx.x;
    if (a >= TT * KK) return;
    const int e = g_topk_idx[a];
    const int pos = atomicAdd(&g_counts[e], 1);
    if (pos < CAP) {
        g_slot_tok[e * CAP + pos] = a / KK;
        g_slot_aid[e * CAP + pos] = a;
        g_valid[a] = 1;
    } else {
        g_valid[a] = 0;
    }
}

// ================= generic split-bf16 mma.sync GEMM =================
// CTA tile 128x128, K chunks of 32, 512 threads = 16 warps (4x4),
// warp tile 32x32. A: [128][40] bf16 hi/lo (row-major, padded).
// B: [32][136] bf16 hi/lo (K-major, padded) -> ldmatrix.trans.
//
// AMODE: 0 = gather rows of x via g_slot_tok (fp32, lda=K)
//        1 = dense fp32 A (x), lda=K
//        2 = pre-split bf16 A (g_h_* if GROUPED else g_sh*), lda=K
// EMODE: 0 = fp32 -> g_G[(e*CAP+s)*ID]            (routed gate)
//        4 = read g_G, swiglu, split -> g_h_hi/lo  (routed up)
//        1 = fp32 scatter by aid -> g_outa          (routed down)
//        2 = fp32 -> g_sG[t*ID]                     (shared gate)
//        5 = read g_sG, swiglu, split -> g_shh/l    (shared up)
//        3 = fp32 + routed combine -> Cf (out)      (shared down)

#define APAD 40
#define BPAD 136
#define STAGE_B (2 * 128 * APAD * 2 + 2 * 32 * BPAD * 2)   // 37888
#define OFF_AL  (128 * APAD * 2)                            // 10240
#define OFF_BH  (2 * 128 * APAD * 2)                        // 20480
#define OFF_BL  (OFF_BH + 32 * BPAD * 2)                    // 29184
#define GEMM_SMEM (2 * STAGE_B)                             // 75776

template<int AMODE, int EMODE, int GROUPED>
__global__ void __launch_bounds__(512, 1)
mma_gemm(const float* __restrict__ Af,
         const float* __restrict__ Bg, long long bstride, int ldb, int K,
         float* __restrict__ Cf, int ldc)
{
    const int e = GROUPED ? blockIdx.z : 0;
    const int cnt = GROUPED ? min(g_counts[e], CAP) : TT;
    const int m0 = blockIdx.y * 128;
    if (m0 >= cnt) return;
    const int n0 = blockIdx.x * 128;

    extern __shared__ char sm[];
    __shared__ int toks[128];
    __shared__ int aids[128];

    const int tid  = threadIdx.x;
    const int lane = tid & 31;
    const int wid  = tid >> 5;
    const int wm   = wid & 3;
    const int wn   = wid >> 2;

    if (tid < 128) {
        const int s = m0 + tid;
        if (AMODE == 0) toks[tid] = (s < cnt) ? g_slot_tok[e * CAP + s] : -1;
        if (EMODE == 1) aids[tid] = (s < cnt) ? g_slot_aid[e * CAP + s] : -1;
    }
    __syncthreads();

    // ---- A staging pointers ----
    const int arow = tid >> 2;            // 4 threads per row
    const int acs  = (tid & 3) * 8;       // col start (8 elems per thread)
    const float* aptr = nullptr;
    const __nv_bfloat16 *ahp = nullptr, *alp = nullptr;
    if (AMODE == 0) {
        const int tk = toks[arow];
        aptr = (tk >= 0) ? Af + (size_t)tk * K : nullptr;
    } else if (AMODE == 1) {
        aptr = Af + (size_t)(m0 + arow) * K;
    } else {
        const size_t r = (GROUPED ? (size_t)e * CAP : 0) + m0 + arow;
        if (GROUPED) { ahp = g_h_hi + r * K; alp = g_h_lo + r * K; }
        else         { ahp = g_shh  + r * K; alp = g_shl  + r * K; }
    }
    const float* Bp = Bg + (GROUPED ? (size_t)e * bstride : 0);

    // staging registers
    float arf[8];
    uint4 ahr, alr;
    float brf[8];

    auto LOAD_REGS = [&](int k0) {
        if (AMODE <= 1) {
            #pragma unroll
            for (int i = 0; i < 2; ++i) {
                float4 v = make_float4(0.f, 0.f, 0.f, 0.f);
                if (AMODE == 1 || aptr)
                    v = *reinterpret_cast<const float4*>(aptr + k0 + acs + i * 4);
                arf[i*4+0] = v.x; arf[i*4+1] = v.y; arf[i*4+2] = v.z; arf[i*4+3] = v.w;
            }
        } else {
            ahr = *reinterpret_cast<const uint4*>(ahp + k0 + acs);
            alr = *reinterpret_cast<const uint4*>(alp + k0 + acs);
        }
        #pragma unroll
        for (int i = 0; i < 2; ++i) {
            const int task = tid + 512 * i;      // 1024 tasks
            const int k  = task >> 5;
            const int nq = task & 31;
            const float4 v = *reinterpret_cast<const float4*>(
                Bp + (size_t)(k0 + k) * ldb + n0 + nq * 4);
            brf[i*4+0] = v.x; brf[i*4+1] = v.y; brf[i*4+2] = v.z; brf[i*4+3] = v.w;
        }
    };

    auto STORE_SM = [&](int buf) {
        char* st = sm + buf * STAGE_B;
        __nv_bfloat16* Ah = (__nv_bfloat16*)(st);
        __nv_bfloat16* Al = (__nv_bfloat16*)(st + OFF_AL);
        __nv_bfloat16* Bh = (__nv_bfloat16*)(st + OFF_BH);
        __nv_bfloat16* Bl = (__nv_bfloat16*)(st + OFF_BL);
        if (AMODE <= 1) {
            #pragma unroll
            for (int i = 0; i < 2; ++i) {
                unsigned short h[4], l[4];
                #pragma unroll
                for (int j = 0; j < 4; ++j) bsplit(arf[i*4+j], h[j], l[j]);
                *reinterpret_cast<uint2*>(&Ah[arow * APAD + acs + i*4]) =
                    make_uint2(pk(h[0], h[1]), pk(h[2], h[3]));
                *reinterpret_cast<uint2*>(&Al[arow * APAD + acs + i*4]) =
                    make_uint2(pk(l[0], l[1]), pk(l[2], l[3]));
            }
        } else {
            *reinterpret_cast<uint4*>(&Ah[arow * APAD + acs]) = ahr;
            *reinterpret_cast<uint4*>(&Al[arow * APAD + acs]) = alr;
        }
        #pragma unroll
        for (int i = 0; i < 2; ++i) {
            const int task = tid + 512 * i;
            const int k  = task >> 5;
            const int nq = task & 31;
            unsigned short h[4], l[4];
            #pragma unroll
            for (int j = 0; j < 4; ++j) bsplit(brf[i*4+j], h[j], l[j]);
            *reinterpret_cast<uint2*>(&Bh[k * BPAD + nq*4]) =
                make_uint2(pk(h[0], h[1]), pk(h[2], h[3]));
            *reinterpret_cast<uint2*>(&Bl[k * BPAD + nq*4]) =
                make_uint2(pk(l[0], l[1]), pk(l[2], l[3]));
        }
    };

    // per-lane ldmatrix address components
    const uint32_t smb = smem_u32(sm);
    const int a_row16  = (lane & 7) + ((lane >> 3) & 1) * 8;  // row within m16
    const int a_khalf  = lane >> 4;                           // 0/1 -> +8 elems
    const int b_k      = (lane & 7) + ((lane >> 3) & 1) * 8;  // k within k16
    const int b_nhalf  = (lane >> 4) & 1;                     // 0/1 -> +8 cols

    float acc[2][4][4];
    #pragma unroll
    for (int a = 0; a < 2; ++a)
        #pragma unroll
        for (int b = 0; b < 4; ++b)
            #pragma unroll
            for (int c = 0; c < 4; ++c) acc[a][b][c] = 0.f;

    const int NCH = K / 32;
    LOAD_REGS(0);
    STORE_SM(0);
    __syncthreads();

    for (int ch = 0; ch < NCH; ++ch) {
        const int buf = ch & 1;
        if (ch + 1 < NCH) LOAD_REGS((ch + 1) * 32);

        const uint32_t stb = smb + buf * STAGE_B;
        #pragma unroll
        for (int ks = 0; ks < 2; ++ks) {
            uint32_t ah[2][4], al[2][4];
            #pragma unroll
            for (int mt = 0; mt < 2; ++mt) {
                const uint32_t aoff =
                    (uint32_t)((wm*32 + mt*16 + a_row16) * (APAD*2) + ks*32 + a_khalf*16);
                ldsm4(ah[mt], stb + aoff);
                ldsm4(al[mt], stb + OFF_AL + aoff);
            }
            #pragma unroll
            for (int ntp = 0; ntp < 2; ++ntp) {
                uint32_t bh[4], bl[4];
                const uint32_t boff =
                    (uint32_t)((ks*16 + b_k) * (BPAD*2) +
                               (wn*32 + ntp*16 + b_nhalf*8) * 2);
                ldsm4t(bh, stb + OFF_BH + boff);
                ldsm4t(bl, stb + OFF_BL + boff);
                #pragma unroll
                for (int half = 0; half < 2; ++half) {
                    const int nt = ntp*2 + half;
                    const uint32_t b0h = bh[half*2], b1h = bh[half*2+1];
                    const uint32_t b0l = bl[half*2], b1l = bl[half*2+1];
                    #pragma unroll
                    for (int mt = 0; mt < 2; ++mt) {
                        mma16816(acc[mt][nt], ah[mt], b0h, b1h);
                        mma16816(acc[mt][nt], ah[mt], b0l, b1l);
                        mma16816(acc[mt][nt], al[mt], b0h, b1h);
                    }
                }
            }
        }
        __syncthreads();
        if (ch + 1 < NCH) { STORE_SM(buf ^ 1); __syncthreads(); }
    }

    // ---- epilogue ----
    const int r0 = lane >> 2;
    const int c0 = (lane & 3) * 2;

    #pragma unroll
    for (int mt = 0; mt < 2; ++mt) {
        #pragma unroll
        for (int rr = 0; rr < 2; ++rr) {
            const int lrow = wm*32 + mt*16 + r0 + rr*8;   // local row 0..127
            const int s    = m0 + lrow;
            if (GROUPED && s >= cnt) continue;

            if (EMODE == 3) {
                // shared down + combine
                float w[KK]; int vd[KK];
                #pragma unroll
                for (int k = 0; k < KK; ++k) {
                    const int a = s * KK + k;
                    vd[k] = g_valid[a];
                    w[k]  = g_topk_w[a];
                }
                #pragma unroll
                for (int nt = 0; nt < 4; ++nt) {
                    const int col = n0 + wn*32 + nt*8 + c0;
                    float o0 = acc[mt][nt][rr*2], o1 = acc[mt][nt][rr*2+1];
                    #pragma unroll
                    for (int k = 0; k < KK; ++k) {
                        if (vd[k]) {
                            const float2 v = *reinterpret_cast<const float2*>(
                                g_outa + (size_t)(s*KK + k) * HD + col);
                            o0 = fmaf(w[k], v.x, o0);
                            o1 = fmaf(w[k], v.y, o1);
                        }
                    }
                    *reinterpret_cast<float2*>(Cf + (size_t)s * ldc + col) =
                        make_float2(o0, o1);
                }
            } else if (EMODE == 1) {
                const int aid = aids[lrow];
                if (aid < 0) continue;
                #pragma unroll
                for (int nt = 0; nt < 4; ++nt) {
                    const int col = n0 + wn*32 + nt*8 + c0;
                    *reinterpret_cast<float2*>(g_outa + (size_t)aid * HD + col) =
                        make_float2(acc[mt][nt][rr*2], acc[mt][nt][rr*2+1]);
                }
            } else if (EMODE == 0 || EMODE == 2) {
                float* base = (EMODE == 0)
                    ? g_G + ((size_t)e * CAP + s) * ldc
                    : g_sG + (size_t)s * ldc;
                #pragma unroll
                for (int nt = 0; nt < 4; ++nt) {
                    const int col = n0 + wn*32 + nt*8 + c0;
                    *reinterpret_cast<float2*>(base + col) =
                        make_float2(acc[mt][nt][rr*2], acc[mt][nt][rr*2+1]);
                }
            } else {
                // EMODE 4/5: fused swiglu + split
                const size_t ridx = (EMODE == 4) ? ((size_t)e * CAP + s) * ID
                                                 : (size_t)s * ID;
                const float* gsrc = (EMODE == 4) ? g_G : g_sG;
                __nv_bfloat16* hh = (EMODE == 4) ? g_h_hi : g_shh;
                __nv_bfloat16* hl = (EMODE == 4) ? g_h_lo : g_shl;
                #pragma unroll
                for (int nt = 0; nt < 4; ++nt) {
                    const int col = n0 + wn*32 + nt*8 + c0;
                    const float2 g = *reinterpret_cast<const float2*>(gsrc + ridx + col);
                    const float h0 = silu(g.x) * acc[mt][nt][rr*2];
                    const float h1 = silu(g.y) * acc[mt][nt][rr*2+1];
                    unsigned short hh0, ll0, hh1, ll1;
                    bsplit(h0, hh0, ll0);
                    bsplit(h1, hh1, ll1);
                    *reinterpret_cast<uint32_t*>(hh + ridx + col) = pk(hh0, hh1);
                    *reinterpret_cast<uint32_t*>(hl + ridx + col) = pk(ll0, ll1);
                }
            }
        }
    }
}

// ---------------- launch ----------------
extern "C" void kernel_launch(void* const* d_in, const int* in_sizes, int n_in,
                              void* d_out, int out_size)
{
    const float* x   = (const float*)d_in[0];
    const float* rw  = (const float*)d_in[1];
    const float* gw  = (const float*)d_in[2];
    const float* uw  = (const float*)d_in[3];
    const float* dw  = (const float*)d_in[4];
    const float* sgw = (const float*)d_in[5];
    const float* suw = (const float*)d_in[6];
    const float* sdw = (const float*)d_in[7];
    float* out = (float*)d_out;

    cudaFuncSetAttribute(mma_gemm<0,0,1>, cudaFuncAttributeMaxDynamicSharedMemorySize, GEMM_SMEM);
    cudaFuncSetAttribute(mma_gemm<0,4,1>, cudaFuncAttributeMaxDynamicSharedMemorySize, GEMM_SMEM);
    cudaFuncSetAttribute(mma_gemm<2,1,1>, cudaFuncAttributeMaxDynamicSharedMemorySize, GEMM_SMEM);
    cudaFuncSetAttribute(mma_gemm<1,2,0>, cudaFuncAttributeMaxDynamicSharedMemorySize, GEMM_SMEM);
    cudaFuncSetAttribute(mma_gemm<1,5,0>, cudaFuncAttributeMaxDynamicSharedMemorySize, GEMM_SMEM);
    cudaFuncSetAttribute(mma_gemm<2,3,0>, cudaFuncAttributeMaxDynamicSharedMemorySize, GEMM_SMEM);

    router_kernel<<<TT, 64>>>(x, rw);
    zero_counts_kernel<<<1, 64>>>();
    assign_kernel<<<(TT * KK + 255) / 256, 256>>>();

    // routed experts
    mma_gemm<0,0,1><<<dim3(ID/128, CAP/128, NE), 512, GEMM_SMEM>>>(
        x, gw, (long long)HD * ID, ID, HD, nullptr, ID);
    mma_gemm<0,4,1><<<dim3(ID/128, CAP/128, NE), 512, GEMM_SMEM>>>(
        x, uw, (long long)HD * ID, ID, HD, nullptr, ID);
    mma_gemm<2,1,1><<<dim3(HD/128, CAP/128, NE), 512, GEMM_SMEM>>>(
        nullptr, dw, (long long)ID * HD, HD, ID, nullptr, HD);

    // shared expert
    mma_gemm<1,2,0><<<dim3(ID/128, TT/128, 1), 512, GEMM_SMEM>>>(
        x, sgw, 0, ID, HD, nullptr, ID);
    mma_gemm<1,5,0><<<dim3(ID/128, TT/128, 1), 512, GEMM_SMEM>>>(
        x, suw, 0, ID, HD, nullptr, ID);
    mma_gemm<2,3,0><<<dim3(HD/128, TT/128, 1), 512, GEMM_SMEM>>>(
        nullptr, sdw, 0, HD, ID, out, HD);
}

// round 10
// speedup vs baseline: 1.0061x; 1.0026x over previous
#include <cuda_runtime.h>
#include <cuda_bf16.h>
#include <math.h>
#include <stdint.h>

// ---------------- problem constants ----------------
#define TT   1024
#define HD   1024
#define NE   64
#define ID   512
#define KK   8
#define NG   8
#define TG   4
#define EG   8
#define CAP  512
#define RSCALE 2.5f

// ---------------- device scratch ----------------
__device__ int   g_topk_idx[TT * KK];
__device__ float g_topk_w[TT * KK];
__device__ int   g_counts[NE];
__device__ int   g_slot_tok[NE * CAP];
__device__ int   g_slot_aid[NE * CAP];
__device__ int   g_valid[TT * KK];
__device__ float g_G[(size_t)NE * CAP * ID];              // gate GEMM out (fp32)
__device__ __nv_bfloat16 g_h_hi[(size_t)NE * CAP * ID];   // swiglu hi
__device__ __nv_bfloat16 g_h_lo[(size_t)NE * CAP * ID];   // swiglu lo
__device__ float g_outa[(size_t)TT * KK * HD];            // per-assignment down out
__device__ float g_sG[(size_t)TT * ID];                   // shared gate out (fp32)
__device__ __nv_bfloat16 g_shh[(size_t)TT * ID];          // shared hidden hi
__device__ __nv_bfloat16 g_shl[(size_t)TT * ID];          // shared hidden lo

// ---------------- helpers ----------------
__device__ __forceinline__ uint32_t smem_u32(const void* p) {
    uint32_t a;
    asm("{ .reg .u64 t; cvta.to.shared.u64 t, %1; cvt.u32.u64 %0, t; }"
        : "=r"(a) : "l"(p));
    return a;
}

__device__ __forceinline__ void bsplit(float a, unsigned short& h, unsigned short& l) {
    __nv_bfloat16 hb = __float2bfloat16(a);
    __nv_bfloat16 lb = __float2bfloat16(a - __bfloat162float(hb));
    h = __bfloat16_as_ushort(hb);
    l = __bfloat16_as_ushort(lb);
}
__device__ __forceinline__ uint32_t pk(unsigned short a, unsigned short b) {
    return (uint32_t)a | ((uint32_t)b << 16);
}

__device__ __forceinline__ void ldsm4(uint32_t* r, uint32_t addr) {
    asm volatile("ldmatrix.sync.aligned.m8n8.x4.shared.b16 {%0,%1,%2,%3}, [%4];"
        : "=r"(r[0]), "=r"(r[1]), "=r"(r[2]), "=r"(r[3]) : "r"(addr));
}
__device__ __forceinline__ void ldsm4t(uint32_t* r, uint32_t addr) {
    asm volatile("ldmatrix.sync.aligned.m8n8.x4.trans.shared.b16 {%0,%1,%2,%3}, [%4];"
        : "=r"(r[0]), "=r"(r[1]), "=r"(r[2]), "=r"(r[3]) : "r"(addr));
}
__device__ __forceinline__ void mma16816(float* d, const uint32_t* a,
                                         uint32_t b0, uint32_t b1) {
    asm volatile(
        "mma.sync.aligned.m16n8k16.row.col.f32.bf16.bf16.f32 "
        "{%0,%1,%2,%3}, {%4,%5,%6,%7}, {%8,%9}, {%0,%1,%2,%3};"
        : "+f"(d[0]), "+f"(d[1]), "+f"(d[2]), "+f"(d[3])
        : "r"(a[0]), "r"(a[1]), "r"(a[2]), "r"(a[3]), "r"(b0), "r"(b1));
}

__device__ __forceinline__ float silu(float g) { return g / (1.f + expf(-g)); }

// ---------------- router ----------------
__global__ void router_kernel(const float* __restrict__ x,
                              const float* __restrict__ rw)
{
    const int t = blockIdx.x;
    __shared__ float xs[HD];
    __shared__ float sc[NE];
    __shared__ float ms[NE];
    __shared__ float gm[NG];
    __shared__ int   selg[NG];

    for (int i = threadIdx.x; i < HD; i += blockDim.x)
        xs[i] = x[(size_t)t * HD + i];
    __syncthreads();

    const int e = threadIdx.x;
    if (e < NE) {
        float acc = 0.f;
        #pragma unroll 8
        for (int h = 0; h < HD; ++h)
            acc = fmaf(xs[h], rw[(size_t)h * NE + e], acc);
        sc[e] = 1.f / (1.f + expf(-acc));
    }
    __syncthreads();

    if (threadIdx.x == 0) {
        for (int g = 0; g < NG; ++g) {
            float m = sc[g * EG];
            for (int j = 1; j < EG; ++j) m = fmaxf(m, sc[g * EG + j]);
            gm[g] = m; selg[g] = 0;
        }
        for (int r = 0; r < TG; ++r) {
            int bi = -1; float bv = -1e30f;
            for (int g = 0; g < NG; ++g)
                if (!selg[g] && gm[g] > bv) { bv = gm[g]; bi = g; }
            selg[bi] = 1;
        }
        for (int ee = 0; ee < NE; ++ee)
            ms[ee] = selg[ee / EG] ? sc[ee] : 0.0f;

        int   idx[KK];
        float val[KK];
        float sum = 0.f;
        for (int r = 0; r < KK; ++r) {
            int bi = 0; float bv = ms[0];
            for (int ee = 1; ee < NE; ++ee)
                if (ms[ee] > bv) { bv = ms[ee]; bi = ee; }
            idx[r] = bi; val[r] = bv; ms[bi] = -1.f; sum += bv;
        }
        const float inv = RSCALE / fmaxf(sum, 1e-9f);
        for (int r = 0; r < KK; ++r) {
            g_topk_idx[t * KK + r] = idx[r];
            g_topk_w[t * KK + r]   = val[r] * inv;
        }
    }
}

__global__ void zero_counts_kernel()
{
    if (threadIdx.x < NE) g_counts[threadIdx.x] = 0;
}

__global__ void assign_kernel()
{
    const int a = blockIdx.x * blockDim.x + threadIdx.x;
    if (a >= TT * KK) return;
    const int e = g_topk_idx[a];
    const int pos = atomicAdd(&g_counts[e], 1);
    if (pos < CAP) {
        g_slot_tok[e * CAP + pos] = a / KK;
        g_slot_aid[e * CAP + pos] = a;
        g_valid[a] = 1;
    } else {
        g_valid[a] = 0;
    }
}

// ================= generic split-bf16 mma.sync GEMM =================
// CTA tile 128x128, K chunks of 32, 512 threads = 16 warps (4x4),
// warp tile 32x32. A: [128][40] bf16 hi/lo (row-major, padded).
// B: [32][136] bf16 hi/lo (K-major, padded) -> ldmatrix.trans.
//
// AMODE: 0 = gather rows of x via g_slot_tok (fp32, lda=K)
//        1 = dense fp32 A (x), lda=K
//        2 = pre-split bf16 A (g_h_* if GROUPED else g_sh*), lda=K
// EMODE: 0 = fp32 -> g_G[(e*CAP+s)*ID]            (routed gate)
//        4 = read g_G, swiglu, split -> g_h_hi/lo  (routed up)
//        1 = fp32 scatter by aid -> g_outa          (routed down)
//        2 = fp32 -> g_sG[t*ID]                     (shared gate)
//        5 = read g_sG, swiglu, split -> g_shh/l    (shared up)
//        3 = fp32 + routed combine -> Cf (out)      (shared down)

#define APAD 40
#define BPAD 136
#define STAGE_B (2 * 128 * APAD * 2 + 2 * 32 * BPAD * 2)   // 37888
#define OFF_AL  (128 * APAD * 2)                            // 10240
#define OFF_BH  (2 * 128 * APAD * 2)                        // 20480
#define OFF_BL  (OFF_BH + 32 * BPAD * 2)                    // 29184
#define GEMM_SMEM (2 * STAGE_B)                             // 75776

template<int AMODE, int EMODE, int GROUPED>
__global__ void __launch_bounds__(512, 1)
mma_gemm(const float* __restrict__ Af,
         const float* __restrict__ Bg, long long bstride, int ldb, int K,
         float* __restrict__ Cf, int ldc)
{
    const int e = GROUPED ? blockIdx.z : 0;
    const int cnt = GROUPED ? min(g_counts[e], CAP) : TT;
    const int m0 = blockIdx.y * 128;
    if (m0 >= cnt) return;
    const int n0 = blockIdx.x * 128;

    extern __shared__ char sm[];
    __shared__ int toks[128];
    __shared__ int aids[128];

    const int tid  = threadIdx.x;
    const int lane = tid & 31;
    const int wid  = tid >> 5;
    const int wm   = wid & 3;
    const int wn   = wid >> 2;

    if (tid < 128) {
        const int s = m0 + tid;
        if (AMODE == 0) toks[tid] = (s < cnt) ? g_slot_tok[e * CAP + s] : -1;
        if (EMODE == 1) aids[tid] = (s < cnt) ? g_slot_aid[e * CAP + s] : -1;
    }
    __syncthreads();

    // ---- A staging pointers ----
    const int arow = tid >> 2;            // 4 threads per row
    const int acs  = (tid & 3) * 8;       // col start (8 elems per thread)
    const float* aptr = nullptr;
    const __nv_bfloat16 *ahp = nullptr, *alp = nullptr;
    if (AMODE == 0) {
        const int tk = toks[arow];
        aptr = (tk >= 0) ? Af + (size_t)tk * K : nullptr;
    } else if (AMODE == 1) {
        aptr = Af + (size_t)(m0 + arow) * K;
    } else {
        const size_t r = (GROUPED ? (size_t)e * CAP : 0) + m0 + arow;
        if (GROUPED) { ahp = g_h_hi + r * K; alp = g_h_lo + r * K; }
        else         { ahp = g_shh  + r * K; alp = g_shl  + r * K; }
    }
    const float* Bp = Bg + (GROUPED ? (size_t)e * bstride : 0);

    // staging registers
    float arf[8];
    uint4 ahr, alr;
    float brf[8];

    auto LOAD_REGS = [&](int k0) {
        if (AMODE <= 1) {
            #pragma unroll
            for (int i = 0; i < 2; ++i) {
                float4 v = make_float4(0.f, 0.f, 0.f, 0.f);
                if (AMODE == 1 || aptr)
                    v = *reinterpret_cast<const float4*>(aptr + k0 + acs + i * 4);
                arf[i*4+0] = v.x; arf[i*4+1] = v.y; arf[i*4+2] = v.z; arf[i*4+3] = v.w;
            }
        } else {
            ahr = *reinterpret_cast<const uint4*>(ahp + k0 + acs);
            alr = *reinterpret_cast<const uint4*>(alp + k0 + acs);
        }
        #pragma unroll
        for (int i = 0; i < 2; ++i) {
            const int task = tid + 512 * i;      // 1024 tasks
            const int k  = task >> 5;
            const int nq = task & 31;
            const float4 v = *reinterpret_cast<const float4*>(
                Bp + (size_t)(k0 + k) * ldb + n0 + nq * 4);
            brf[i*4+0] = v.x; brf[i*4+1] = v.y; brf[i*4+2] = v.z; brf[i*4+3] = v.w;
        }
    };

    auto STORE_SM = [&](int buf) {
        char* st = sm + buf * STAGE_B;
        __nv_bfloat16* Ah = (__nv_bfloat16*)(st);
        __nv_bfloat16* Al = (__nv_bfloat16*)(st + OFF_AL);
        __nv_bfloat16* Bh = (__nv_bfloat16*)(st + OFF_BH);
        __nv_bfloat16* Bl = (__nv_bfloat16*)(st + OFF_BL);
        if (AMODE <= 1) {
            #pragma unroll
            for (int i = 0; i < 2; ++i) {
                unsigned short h[4], l[4];
                #pragma unroll
                for (int j = 0; j < 4; ++j) bsplit(arf[i*4+j], h[j], l[j]);
                *reinterpret_cast<uint2*>(&Ah[arow * APAD + acs + i*4]) =
                    make_uint2(pk(h[0], h[1]), pk(h[2], h[3]));
                *reinterpret_cast<uint2*>(&Al[arow * APAD + acs + i*4]) =
                    make_uint2(pk(l[0], l[1]), pk(l[2], l[3]));
            }
        } else {
            *reinterpret_cast<uint4*>(&Ah[arow * APAD + acs]) = ahr;
            *reinterpret_cast<uint4*>(&Al[arow * APAD + acs]) = alr;
        }
        #pragma unroll
        for (int i = 0; i < 2; ++i) {
            const int task = tid + 512 * i;
            const int k  = task >> 5;
            const int nq = task & 31;
            unsigned short h[4], l[4];
            #pragma unroll
            for (int j = 0; j < 4; ++j) bsplit(brf[i*4+j], h[j], l[j]);
            *reinterpret_cast<uint2*>(&Bh[k * BPAD + nq*4]) =
                make_uint2(pk(h[0], h[1]), pk(h[2], h[3]));
            *reinterpret_cast<uint2*>(&Bl[k * BPAD + nq*4]) =
                make_uint2(pk(l[0], l[1]), pk(l[2], l[3]));
        }
    };

    // per-lane ldmatrix address components
    const uint32_t smb = smem_u32(sm);
    const int a_row16  = (lane & 7) + ((lane >> 3) & 1) * 8;  // row within m16
    const int a_khalf  = lane >> 4;                           // 0/1 -> +8 elems
    const int b_k      = (lane & 7) + ((lane >> 3) & 1) * 8;  // k within k16
    const int b_nhalf  = (lane >> 4) & 1;                     // 0/1 -> +8 cols

    float acc[2][4][4];
    #pragma unroll
    for (int a = 0; a < 2; ++a)
        #pragma unroll
        for (int b = 0; b < 4; ++b)
            #pragma unroll
            for (int c = 0; c < 4; ++c) acc[a][b][c] = 0.f;

    const int NCH = K / 32;
    LOAD_REGS(0);
    STORE_SM(0);
    __syncthreads();

    for (int ch = 0; ch < NCH; ++ch) {
        const int buf = ch & 1;
        if (ch + 1 < NCH) LOAD_REGS((ch + 1) * 32);

        const uint32_t stb = smb + buf * STAGE_B;
        #pragma unroll
        for (int ks = 0; ks < 2; ++ks) {
            uint32_t ah[2][4], al[2][4];
            #pragma unroll
            for (int mt = 0; mt < 2; ++mt) {
                const uint32_t aoff =
                    (uint32_t)((wm*32 + mt*16 + a_row16) * (APAD*2) + ks*32 + a_khalf*16);
                ldsm4(ah[mt], stb + aoff);
                ldsm4(al[mt], stb + OFF_AL + aoff);
            }
            #pragma unroll
            for (int ntp = 0; ntp < 2; ++ntp) {
                uint32_t bh[4], bl[4];
                const uint32_t boff =
                    (uint32_t)((ks*16 + b_k) * (BPAD*2) +
                               (wn*32 + ntp*16 + b_nhalf*8) * 2);
                ldsm4t(bh, stb + OFF_BH + boff);
                ldsm4t(bl, stb + OFF_BL + boff);
                #pragma unroll
                for (int half = 0; half < 2; ++half) {
                    const int nt = ntp*2 + half;
                    const uint32_t b0h = bh[half*2], b1h = bh[half*2+1];
                    const uint32_t b0l = bl[half*2], b1l = bl[half*2+1];
                    #pragma unroll
                    for (int mt = 0; mt < 2; ++mt) {
                        mma16816(acc[mt][nt], ah[mt], b0h, b1h);
                        mma16816(acc[mt][nt], ah[mt], b0l, b1l);
                        mma16816(acc[mt][nt], al[mt], b0h, b1h);
                    }
                }
            }
        }
        __syncthreads();
        if (ch + 1 < NCH) { STORE_SM(buf ^ 1); __syncthreads(); }
    }

    // ---- epilogue ----
    const int r0 = lane >> 2;
    const int c0 = (lane & 3) * 2;

    #pragma unroll
    for (int mt = 0; mt < 2; ++mt) {
        #pragma unroll
        for (int rr = 0; rr < 2; ++rr) {
            const int lrow = wm*32 + mt*16 + r0 + rr*8;   // local row 0..127
            const int s    = m0 + lrow;
            if (GROUPED && s >= cnt) continue;

            if (EMODE == 3) {
                // shared down + combine
                float w[KK]; int vd[KK];
                #pragma unroll
                for (int k = 0; k < KK; ++k) {
                    const int a = s * KK + k;
                    vd[k] = g_valid[a];
                    w[k]  = g_topk_w[a];
                }
                #pragma unroll
                for (int nt = 0; nt < 4; ++nt) {
                    const int col = n0 + wn*32 + nt*8 + c0;
                    float o0 = acc[mt][nt][rr*2], o1 = acc[mt][nt][rr*2+1];
                    #pragma unroll
                    for (int k = 0; k < KK; ++k) {
                        if (vd[k]) {
                            const float2 v = *reinterpret_cast<const float2*>(
                                g_outa + (size_t)(s*KK + k) * HD + col);
                            o0 = fmaf(w[k], v.x, o0);
                            o1 = fmaf(w[k], v.y, o1);
                        }
                    }
                    *reinterpret_cast<float2*>(Cf + (size_t)s * ldc + col) =
                        make_float2(o0, o1);
                }
            } else if (EMODE == 1) {
                const int aid = aids[lrow];
                if (aid < 0) continue;
                #pragma unroll
                for (int nt = 0; nt < 4; ++nt) {
                    const int col = n0 + wn*32 + nt*8 + c0;
                    *reinterpret_cast<float2*>(g_outa + (size_t)aid * HD + col) =
                        make_float2(acc[mt][nt][rr*2], acc[mt][nt][rr*2+1]);
                }
            } else if (EMODE == 0 || EMODE == 2) {
                float* base = (EMODE == 0)
                    ? g_G + ((size_t)e * CAP + s) * ldc
                    : g_sG + (size_t)s * ldc;
                #pragma unroll
                for (int nt = 0; nt < 4; ++nt) {
                    const int col = n0 + wn*32 + nt*8 + c0;
                    *reinterpret_cast<float2*>(base + col) =
                        make_float2(acc[mt][nt][rr*2], acc[mt][nt][rr*2+1]);
                }
            } else {
                // EMODE 4/5: fused swiglu + split
                const size_t ridx = (EMODE == 4) ? ((size_t)e * CAP + s) * ID
                                                 : (size_t)s * ID;
                const float* gsrc = (EMODE == 4) ? g_G : g_sG;
                __nv_bfloat16* hh = (EMODE == 4) ? g_h_hi : g_shh;
                __nv_bfloat16* hl = (EMODE == 4) ? g_h_lo : g_shl;
                #pragma unroll
                for (int nt = 0; nt < 4; ++nt) {
                    const int col = n0 + wn*32 + nt*8 + c0;
                    const float2 g = *reinterpret_cast<const float2*>(gsrc + ridx + col);
                    const float h0 = silu(g.x) * acc[mt][nt][rr*2];
                    const float h1 = silu(g.y) * acc[mt][nt][rr*2+1];
                    unsigned short hh0, ll0, hh1, ll1;
                    bsplit(h0, hh0, ll0);
                    bsplit(h1, hh1, ll1);
                    *reinterpret_cast<uint32_t*>(hh + ridx + col) = pk(hh0, hh1);
                    *reinterpret_cast<uint32_t*>(hl + ridx + col) = pk(ll0, ll1);
                }
            }
        }
    }
}

// ---------------- launch ----------------
extern "C" void kernel_launch(void* const* d_in, const int* in_sizes, int n_in,
                              void* d_out, int out_size)
{
    const float* x   = (const float*)d_in[0];
    const float* rw  = (const float*)d_in[1];
    const float* gw  = (const float*)d_in[2];
    const float* uw  = (const float*)d_in[3];
    const float* dw  = (const float*)d_in[4];
    const float* sgw = (const float*)d_in[5];
    const float* suw = (const float*)d_in[6];
    const float* sdw = (const float*)d_in[7];
    float* out = (float*)d_out;

    cudaFuncSetAttribute(mma_gemm<0,0,1>, cudaFuncAttributeMaxDynamicSharedMemorySize, GEMM_SMEM);
    cudaFuncSetAttribute(mma_gemm<0,4,1>, cudaFuncAttributeMaxDynamicSharedMemorySize, GEMM_SMEM);
    cudaFuncSetAttribute(mma_gemm<2,1,1>, cudaFuncAttributeMaxDynamicSharedMemorySize, GEMM_SMEM);
    cudaFuncSetAttribute(mma_gemm<1,2,0>, cudaFuncAttributeMaxDynamicSharedMemorySize, GEMM_SMEM);
    cudaFuncSetAttribute(mma_gemm<1,5,0>, cudaFuncAttributeMaxDynamicSharedMemorySize, GEMM_SMEM);
    cudaFuncSetAttribute(mma_gemm<2,3,0>, cudaFuncAttributeMaxDynamicSharedMemorySize, GEMM_SMEM);

    router_kernel<<<TT, 64>>>(x, rw);
    zero_counts_kernel<<<1, 64>>>();
    assign_kernel<<<(TT * KK + 255) / 256, 256>>>();

    // routed experts
    mma_gemm<0,0,1><<<dim3(ID/128, CAP/128, NE), 512, GEMM_SMEM>>>(
        x, gw, (long long)HD * ID, ID, HD, nullptr, ID);
    mma_gemm<0,4,1><<<dim3(ID/128, CAP/128, NE), 512, GEMM_SMEM>>>(
        x, uw, (long long)HD * ID, ID, HD, nullptr, ID);
    mma_gemm<2,1,1><<<dim3(HD/128, CAP/128, NE), 512, GEMM_SMEM>>>(
        nullptr, dw, (long long)ID * HD, HD, ID, nullptr, HD);

    // shared expert
    mma_gemm<1,2,0><<<dim3(ID/128, TT/128, 1), 512, GEMM_SMEM>>>(
        x, sgw, 0, ID, HD, nullptr, ID);
    mma_gemm<1,5,0><<<dim3(ID/128, TT/128, 1), 512, GEMM_SMEM>>>(
        x, suw, 0, ID, HD, nullptr, ID);
    mma_gemm<2,3,0><<<dim3(HD/128, TT/128, 1), 512, GEMM_SMEM>>>(
        nullptr, sdw, 0, HD, ID, out, HD);
}